// round 1
// baseline (speedup 1.0000x reference)
#include <cuda_runtime.h>
#include <cuda_bf16.h>
#include <math.h>

// Problem constants
#define B_  16
#define T_  12
#define N_  325
#define D_  64
#define L_  2
#define G_  192
#define BN  (B_ * N_)          // 5200

// d_out layout (floats): output, hidden, attn_input, attn_hidden
#define SZ_OUT ((size_t)B_ * T_ * N_ * D_)            // 3,993,600
#define SZ_HID ((size_t)B_ * L_ * N_ * D_)            //   665,600
#define SZ_A   ((size_t)B_ * T_ * L_ * N_ * N_)       // 40,560,000
#define OFF_OUT 0
#define OFF_HID (SZ_OUT)
#define OFF_AI  (SZ_OUT + SZ_HID)
#define OFF_AH  (SZ_OUT + SZ_HID + SZ_A)

// Scratch (device globals -- no allocation allowed)
__device__ float g_X[BN * D_];           // current layer input
__device__ float g_Q[2][BN * D_];
__device__ float g_K[2][BN * D_];
__device__ float g_V[2][BN * G_];
__device__ float g_O[2][BN * G_];        // gat outputs (attn@V + bias)

// ---------------------------------------------------------------------------
// Kernel 0: zero the hidden section of d_out (it is the live GRU state)
// ---------------------------------------------------------------------------
__global__ void zero_hidden_kernel(float* __restrict__ outf) {
    size_t i = (size_t)blockIdx.x * blockDim.x + threadIdx.x;
    if (i < SZ_HID) outf[OFF_HID + i] = 0.0f;
}

// ---------------------------------------------------------------------------
// Kernel 1: QKV GEMM.  X:(BN,64) @ {Wq,Wk,Wv} x {input-gat, hidden-gat}
// grid = (ceil(BN/64)=82, 10 column-blocks), block = 256
// column blocks: 0:Qi 1:Ki 2-4:Vi 5:Qh 6:Kh 7-9:Vh
// ---------------------------------------------------------------------------
__global__ void qkv_kernel(int t, int l, int from_x,
                           const float* __restrict__ x,
                           const float* __restrict__ Wq_i, const float* __restrict__ Wk_i,
                           const float* __restrict__ Wv_i,
                           const float* __restrict__ Wq_h, const float* __restrict__ Wk_h,
                           const float* __restrict__ Wv_h) {
    __shared__ float Xs[64][65];
    __shared__ float Ws[64][65];

    const int rb  = blockIdx.x;
    const int cb  = blockIdx.y;
    const int tid = threadIdx.x;

    const float* src;
    long bstr;
    if (from_x) { src = x + (size_t)t * N_ * D_; bstr = (long)T_ * N_ * D_; }
    else        { src = g_X;                     bstr = (long)N_ * D_; }

    // load X tile (64 rows x 64 k)
    for (int idx = tid; idx < 64 * 64; idx += 256) {
        int r = idx >> 6, k = idx & 63;
        int row = rb * 64 + r;
        float v = 0.0f;
        if (row < BN) {
            int bb = row / N_, n = row - bb * N_;
            v = src[(size_t)bb * bstr + n * D_ + k];
        }
        Xs[r][k] = v;
    }

    // select weight slice
    const int g  = (cb >= 5) ? 1 : 0;
    const int c5 = cb - g * 5;
    const float* W; int wcols, coff = 0;
    if (c5 == 0)      { W = (g ? Wq_h : Wq_i) + (size_t)l * D_ * D_; wcols = 64; }
    else if (c5 == 1) { W = (g ? Wk_h : Wk_i) + (size_t)l * D_ * D_; wcols = 64; }
    else              { W = (g ? Wv_h : Wv_i) + (size_t)l * D_ * G_; wcols = G_; coff = (c5 - 2) * 64; }

    for (int idx = tid; idx < 64 * 64; idx += 256) {
        int k = idx >> 6, c = idx & 63;
        Ws[k][c] = W[k * wcols + coff + c];
    }
    __syncthreads();

    const int ty = tid >> 4, tx = tid & 15;
    float acc[4][4] = {};
#pragma unroll 8
    for (int k = 0; k < 64; k++) {
        float xv[4], wv[4];
#pragma unroll
        for (int m = 0; m < 4; m++) xv[m] = Xs[ty + 16 * m][k];
#pragma unroll
        for (int j = 0; j < 4; j++) wv[j] = Ws[k][tx + 16 * j];
#pragma unroll
        for (int m = 0; m < 4; m++)
#pragma unroll
            for (int j = 0; j < 4; j++) acc[m][j] += xv[m] * wv[j];
    }

    float* dst; int dcols, dcoff;
    if (c5 == 0)      { dst = g_Q[g]; dcols = 64;  dcoff = 0; }
    else if (c5 == 1) { dst = g_K[g]; dcols = 64;  dcoff = 0; }
    else              { dst = g_V[g]; dcols = G_;  dcoff = (c5 - 2) * 64; }

#pragma unroll
    for (int m = 0; m < 4; m++) {
        int row = rb * 64 + ty + 16 * m;
        if (row < BN) {
#pragma unroll
            for (int j = 0; j < 4; j++)
                dst[(size_t)row * dcols + dcoff + tx + 16 * j] = acc[m][j];
        }
    }
}

// ---------------------------------------------------------------------------
// Kernel 2: fused attention per (row-tile, gat, batch).
//   S = Q K^T / 8  -> softmax (full 325-wide rows in smem) -> write attn
//   O = P V + bias -> g_O
// block = 256, grid = (11, 2, 16), dynamic smem ~79KB
// ---------------------------------------------------------------------------
#define NPADS 352   // padded key width (11 chunks of 32)

__global__ void attn_kernel(int t, int l,
                            const float* __restrict__ b_i, const float* __restrict__ b_h,
                            float* __restrict__ outf) {
    extern __shared__ float sm[];
    float* Qs = sm;                      // 32*65
    float* S  = sm + 32 * 65;            // 32*NPADS
    float* CH = S + 32 * NPADS;          // chunk: max(64*66, 32*200) = 6400

    const int rt  = blockIdx.x;
    const int g   = blockIdx.y;
    const int b   = blockIdx.z;
    const int tid = threadIdx.x;
    const int r0  = rt * 32;

    const float* Qg = g_Q[g] + (size_t)b * N_ * D_;
    const float* Kg = g_K[g] + (size_t)b * N_ * D_;
    const float* Vg = g_V[g] + (size_t)b * N_ * G_;

    // load Q tile
    for (int idx = tid; idx < 32 * 64; idx += 256) {
        int r = idx >> 6, d = idx & 63;
        int qr = r0 + r;
        Qs[r * 65 + d] = (qr < N_) ? Qg[(size_t)qr * D_ + d] : 0.0f;
    }

    // ----- Phase 1: scores -----
    const int ty = tid >> 4, tx = tid & 15;
    for (int kc = 0; kc < 6; kc++) {
        int kb = kc * 64;
        __syncthreads();
        for (int idx = tid; idx < 64 * 64; idx += 256) {
            int kk = idx >> 6, d = idx & 63;
            int key = kb + kk;
            CH[kk * 66 + d] = (key < N_) ? Kg[(size_t)key * D_ + d] : 0.0f;
        }
        __syncthreads();

        float acc0[4] = {}, acc1[4] = {};
#pragma unroll 8
        for (int k = 0; k < 64; k++) {
            float q0 = Qs[ty * 65 + k];
            float q1 = Qs[(ty + 16) * 65 + k];
#pragma unroll
            for (int j = 0; j < 4; j++) {
                float kv = CH[(tx + 16 * j) * 66 + k];
                acc0[j] += q0 * kv;
                acc1[j] += q1 * kv;
            }
        }
#pragma unroll
        for (int j = 0; j < 4; j++) {
            int c = kb + tx + 16 * j;
            if (c < N_) {
                S[ty * NPADS + c]        = acc0[j] * 0.125f;
                S[(ty + 16) * NPADS + c] = acc1[j] * 0.125f;
            }
        }
    }
    __syncthreads();

    // ----- Softmax (8 warps, 4 rows each) + write attn to d_out -----
    const int w = tid >> 5, lane = tid & 31;
    const size_t attn_base = (g == 0 ? OFF_AI : OFF_AH);
    for (int rr = w; rr < 32; rr += 8) {
        int qr = r0 + rr;
        if (qr < N_) {
            float mx = -1e30f;
            for (int i = lane; i < N_; i += 32) mx = fmaxf(mx, S[rr * NPADS + i]);
#pragma unroll
            for (int o = 16; o; o >>= 1) mx = fmaxf(mx, __shfl_xor_sync(0xffffffffu, mx, o));
            float s = 0.0f;
            for (int i = lane; i < NPADS; i += 32) {
                if (i < N_) {
                    float e = __expf(S[rr * NPADS + i] - mx);
                    S[rr * NPADS + i] = e;
                    s += e;
                } else S[rr * NPADS + i] = 0.0f;
            }
#pragma unroll
            for (int o = 16; o; o >>= 1) s += __shfl_xor_sync(0xffffffffu, s, o);
            float inv = 1.0f / s;
            float* arow = outf + attn_base +
                ((((size_t)b * T_ + t) * L_ + l) * N_ + qr) * (size_t)N_;
            for (int i = lane; i < N_; i += 32) {
                float p = S[rr * NPADS + i] * inv;
                S[rr * NPADS + i] = p;
                arow[i] = p;
            }
        } else {
            for (int i = lane; i < NPADS; i += 32) S[rr * NPADS + i] = 0.0f;
        }
    }

    // ----- Phase 2: O = P V -----
    const int ry = tid >> 5, cx = tid & 31;
    float acc[4][6] = {};
    for (int kc = 0; kc < 11; kc++) {
        int kb = kc * 32;
        __syncthreads();
        for (int idx = tid; idx < 32 * 48; idx += 256) {
            int kk = idx / 48, f4 = idx % 48;
            int key = kb + kk;
            float4 v = make_float4(0.f, 0.f, 0.f, 0.f);
            if (key < N_)
                v = *(const float4*)(Vg + (size_t)key * G_ + f4 * 4);
            *(float4*)(&CH[kk * 200 + f4 * 4]) = v;
        }
        __syncthreads();
#pragma unroll 4
        for (int kk = 0; kk < 32; kk++) {
            float p0 = S[(ry)      * NPADS + kb + kk];
            float p1 = S[(ry + 8)  * NPADS + kb + kk];
            float p2 = S[(ry + 16) * NPADS + kb + kk];
            float p3 = S[(ry + 24) * NPADS + kb + kk];
#pragma unroll
            for (int j = 0; j < 6; j++) {
                float v = CH[kk * 200 + cx + 32 * j];
                acc[0][j] += p0 * v;
                acc[1][j] += p1 * v;
                acc[2][j] += p2 * v;
                acc[3][j] += p3 * v;
            }
        }
    }

    const float* bias = (g == 0 ? b_i : b_h) + (size_t)l * G_;
    float* Og = g_O[g] + (size_t)b * N_ * G_;
#pragma unroll
    for (int m = 0; m < 4; m++) {
        int qr = r0 + ry + 8 * m;
        if (qr < N_) {
#pragma unroll
            for (int j = 0; j < 6; j++) {
                int c = cx + 32 * j;
                Og[(size_t)qr * G_ + c] = acc[m][j] + bias[c];
            }
        }
    }
}

// ---------------------------------------------------------------------------
// Kernel 3: GRU gating + LayerNorm. block = 256 (4 rows x 64), grid = 1300
// ---------------------------------------------------------------------------
__global__ void gate_kernel(int t, int l,
                            const float* __restrict__ ln_g, const float* __restrict__ ln_b,
                            float* __restrict__ outf) {
    __shared__ float s_s[8], s_q[8];
    const int tid  = threadIdx.x;
    const int rloc = tid >> 6;
    const int d    = tid & 63;
    const int row  = blockIdx.x * 4 + rloc;
    const int valid = (row < BN);

    float o = 0.0f;
    int b = 0, n = 0;
    if (valid) {
        b = row / N_; n = row - b * N_;
        const float* oi = g_O[0] + (size_t)row * G_;
        const float* oh = g_O[1] + (size_t)row * G_;
        const float* hid = outf + OFF_HID + (((size_t)b * L_ + l) * N_ + n) * D_;
        float h  = hid[d];
        float rg = 1.0f / (1.0f + expf(-(oi[d]       + oh[d])));
        float ig = 1.0f / (1.0f + expf(-(oi[64 + d]  + oh[64 + d])));
        float ng = tanhf(oi[128 + d] + rg * oh[128 + d]);
        o = ng + ig * (h - ng);
    }

    float s = o, q = o * o;
#pragma unroll
    for (int off = 16; off; off >>= 1) {
        s += __shfl_xor_sync(0xffffffffu, s, off);
        q += __shfl_xor_sync(0xffffffffu, q, off);
    }
    const int w = tid >> 5;
    if ((tid & 31) == 0) { s_s[w] = s; s_q[w] = q; }
    __syncthreads();

    if (valid) {
        int w0 = rloc * 2;
        float sum = s_s[w0] + s_s[w0 + 1];
        float sq  = s_q[w0] + s_q[w0 + 1];
        float mu  = sum * (1.0f / 64.0f);
        float var = sq * (1.0f / 64.0f) - mu * mu;
        float y = (o - mu) * rsqrtf(var + 1e-5f) * ln_g[l * D_ + d] + ln_b[l * D_ + d];
        float* hid = outf + OFF_HID + (((size_t)b * L_ + l) * N_ + n) * D_;
        hid[d] = y;
        g_X[(size_t)row * D_ + d] = y;
        if (l == L_ - 1)
            outf[(((size_t)b * T_ + t) * N_ + n) * D_ + d] = y;
    }
}

// ---------------------------------------------------------------------------
extern "C" void kernel_launch(void* const* d_in, const int* in_sizes, int n_in,
                              void* d_out, int out_size) {
    const float* x    = (const float*)d_in[0];
    const float* Wq_i = (const float*)d_in[1];
    const float* Wk_i = (const float*)d_in[2];
    const float* Wv_i = (const float*)d_in[3];
    const float* b_i  = (const float*)d_in[4];
    const float* Wq_h = (const float*)d_in[5];
    const float* Wk_h = (const float*)d_in[6];
    const float* Wv_h = (const float*)d_in[7];
    const float* b_h  = (const float*)d_in[8];
    const float* ln_g = (const float*)d_in[9];
    const float* ln_b = (const float*)d_in[10];
    float* outf = (float*)d_out;

    const int attn_smem = (32 * 65 + 32 * NPADS + 6400) * (int)sizeof(float); // 78,976 B
    cudaFuncSetAttribute(attn_kernel, cudaFuncAttributeMaxDynamicSharedMemorySize, attn_smem);

    zero_hidden_kernel<<<(int)((SZ_HID + 255) / 256), 256>>>(outf);

    dim3 qkv_grid(82, 10);
    dim3 attn_grid(11, 2, 16);
    const int gate_grid = (BN + 3) / 4;

    for (int t = 0; t < T_; t++) {
        for (int l = 0; l < L_; l++) {
            int from_x = (l == 0) ? 1 : 0;
            qkv_kernel<<<qkv_grid, 256>>>(t, l, from_x, x,
                                          Wq_i, Wk_i, Wv_i, Wq_h, Wk_h, Wv_h);
            attn_kernel<<<attn_grid, 256, attn_smem>>>(t, l, b_i, b_h, outf);
            gate_kernel<<<gate_grid, 256>>>(t, l, ln_g, ln_b, outf);
        }
    }
}

// round 2
// speedup vs baseline: 1.5407x; 1.5407x over previous
#include <cuda_runtime.h>
#include <cuda_bf16.h>
#include <math.h>

// Problem constants
#define B_  16
#define T_  12
#define N_  325
#define D_  64
#define L_  2
#define G_  192
#define BN  (B_ * N_)          // 5200

// d_out layout (floats): output, hidden, attn_input, attn_hidden
#define SZ_OUT ((size_t)B_ * T_ * N_ * D_)
#define SZ_HID ((size_t)B_ * L_ * N_ * D_)
#define SZ_A   ((size_t)B_ * T_ * L_ * N_ * N_)
#define OFF_OUT 0
#define OFF_HID (SZ_OUT)
#define OFF_AI  (SZ_OUT + SZ_HID)
#define OFF_AH  (SZ_OUT + SZ_HID + SZ_A)

// Scratch (device globals -- no allocation allowed)
__device__ float g_X[BN * D_];
__device__ float g_Q[2][BN * D_];
__device__ float g_K[2][BN * D_];
__device__ float g_V[2][BN * G_];
__device__ float g_O[2][BN * G_];

// ---------------------------------------------------------------------------
__global__ void zero_hidden_kernel(float* __restrict__ outf) {
    size_t i = (size_t)blockIdx.x * blockDim.x + threadIdx.x;
    if (i < SZ_HID) outf[OFF_HID + i] = 0.0f;
}

// ---------------------------------------------------------------------------
// QKV GEMM (already FMA/LDS balanced): grid (82, 10), block 256
// ---------------------------------------------------------------------------
__global__ void qkv_kernel(int t, int l, int from_x,
                           const float* __restrict__ x,
                           const float* __restrict__ Wq_i, const float* __restrict__ Wk_i,
                           const float* __restrict__ Wv_i,
                           const float* __restrict__ Wq_h, const float* __restrict__ Wk_h,
                           const float* __restrict__ Wv_h) {
    __shared__ float Xs[64][65];
    __shared__ float Ws[64][65];

    const int rb  = blockIdx.x;
    const int cb  = blockIdx.y;
    const int tid = threadIdx.x;

    const float* src;
    long bstr;
    if (from_x) { src = x + (size_t)t * N_ * D_; bstr = (long)T_ * N_ * D_; }
    else        { src = g_X;                     bstr = (long)N_ * D_; }

    for (int idx = tid; idx < 64 * 64; idx += 256) {
        int r = idx >> 6, k = idx & 63;
        int row = rb * 64 + r;
        float v = 0.0f;
        if (row < BN) {
            int bb = row / N_, n = row - bb * N_;
            v = src[(size_t)bb * bstr + n * D_ + k];
        }
        Xs[r][k] = v;
    }

    const int g  = (cb >= 5) ? 1 : 0;
    const int c5 = cb - g * 5;
    const float* W; int wcols, coff = 0;
    if (c5 == 0)      { W = (g ? Wq_h : Wq_i) + (size_t)l * D_ * D_; wcols = 64; }
    else if (c5 == 1) { W = (g ? Wk_h : Wk_i) + (size_t)l * D_ * D_; wcols = 64; }
    else              { W = (g ? Wv_h : Wv_i) + (size_t)l * D_ * G_; wcols = G_; coff = (c5 - 2) * 64; }

    for (int idx = tid; idx < 64 * 64; idx += 256) {
        int k = idx >> 6, c = idx & 63;
        Ws[k][c] = W[k * wcols + coff + c];
    }
    __syncthreads();

    const int ty = tid >> 4, tx = tid & 15;
    float acc[4][4] = {};
#pragma unroll 8
    for (int k = 0; k < 64; k++) {
        float xv[4], wv[4];
#pragma unroll
        for (int m = 0; m < 4; m++) xv[m] = Xs[ty + 16 * m][k];
#pragma unroll
        for (int j = 0; j < 4; j++) wv[j] = Ws[k][tx + 16 * j];
#pragma unroll
        for (int m = 0; m < 4; m++)
#pragma unroll
            for (int j = 0; j < 4; j++) acc[m][j] += xv[m] * wv[j];
    }

    float* dst; int dcols, dcoff;
    if (c5 == 0)      { dst = g_Q[g]; dcols = 64;  dcoff = 0; }
    else if (c5 == 1) { dst = g_K[g]; dcols = 64;  dcoff = 0; }
    else              { dst = g_V[g]; dcols = G_;  dcoff = (c5 - 2) * 64; }

#pragma unroll
    for (int m = 0; m < 4; m++) {
        int row = rb * 64 + ty + 16 * m;
        if (row < BN) {
#pragma unroll
            for (int j = 0; j < 4; j++)
                dst[(size_t)row * dcols + dcoff + tx + 16 * j] = acc[m][j];
        }
    }
}

// ---------------------------------------------------------------------------
// Fused attention, FMA-bound tiling.
//   RT=40 query rows per block; warp w owns rows w+8m (broadcast smem reads).
//   Phase1: K chunks of 128, per-thread 5x4 tile. Phase2: V chunks of 32,
//   per-thread 5x6 tile, float4 P loads. grid (9, 2, 16), block 256.
// ---------------------------------------------------------------------------
#define RT     40
#define NTILES 9
#define NPADS  352
#define QSTR   68
#define KSTR   65
#define VSTR   196

#define ATTN_SMEM_FLOATS (RT * QSTR + RT * NPADS + 128 * KSTR)

__global__ void attn_kernel(int t, int l,
                            const float* __restrict__ b_i, const float* __restrict__ b_h,
                            float* __restrict__ outf) {
    extern __shared__ float sm[];
    float* Qs = sm;                         // RT x QSTR
    float* S  = sm + RT * QSTR;             // RT x NPADS
    float* CH = S + RT * NPADS;             // K: 128 x KSTR  /  V: 32 x VSTR

    const int rt   = blockIdx.x;
    const int g    = blockIdx.y;
    const int b    = blockIdx.z;
    const int tid  = threadIdx.x;
    const int w    = tid >> 5;
    const int lane = tid & 31;
    const int r0   = rt * RT;

    const float* Qg = g_Q[g] + (size_t)b * N_ * D_;
    const float* Kg = g_K[g] + (size_t)b * N_ * D_;
    const float* Vg = g_V[g] + (size_t)b * N_ * G_;

    // load Q tile
    for (int idx = tid; idx < RT * 64; idx += 256) {
        int r = idx >> 6, d = idx & 63;
        int qr = r0 + r;
        Qs[r * QSTR + d] = (qr < N_) ? Qg[(size_t)qr * D_ + d] : 0.0f;
    }

    // ----- Phase 1: S = Q K^T / 8 -----
    for (int kc = 0; kc < 3; kc++) {
        const int kb = kc * 128;
        __syncthreads();
        // load 128-key chunk, float4 from global, scalar STS (KSTR=65 conflict-free reads)
        for (int idx = tid; idx < 128 * 16; idx += 256) {
            int key = idx >> 4, d4 = idx & 15;
            int gk = kb + key;
            float4 v = make_float4(0.f, 0.f, 0.f, 0.f);
            if (gk < N_) v = *(const float4*)(Kg + (size_t)gk * D_ + 4 * d4);
            int base = key * KSTR + 4 * d4;
            CH[base] = v.x; CH[base + 1] = v.y; CH[base + 2] = v.z; CH[base + 3] = v.w;
        }
        __syncthreads();

        float acc[5][4] = {};
#pragma unroll
        for (int k = 0; k < 64; k += 4) {
            float4 q[5];
#pragma unroll
            for (int m = 0; m < 5; m++)
                q[m] = *(const float4*)&Qs[(w + 8 * m) * QSTR + k];
#pragma unroll
            for (int j = 0; j < 4; j++) {
                const int ck = (lane + 32 * j) * KSTR + k;
                float k0 = CH[ck], k1 = CH[ck + 1], k2 = CH[ck + 2], k3 = CH[ck + 3];
#pragma unroll
                for (int m = 0; m < 5; m++)
                    acc[m][j] += q[m].x * k0 + q[m].y * k1 + q[m].z * k2 + q[m].w * k3;
            }
        }
#pragma unroll
        for (int j = 0; j < 4; j++) {
            int c = kb + lane + 32 * j;
            if (c < NPADS) {
#pragma unroll
                for (int m = 0; m < 5; m++)
                    S[(w + 8 * m) * NPADS + c] = acc[m][j] * 0.125f;
            }
        }
    }
    __syncthreads();

    // ----- Softmax + write attn to d_out -----
    const size_t attn_base = (g == 0 ? OFF_AI : OFF_AH);
    for (int rr = w; rr < RT; rr += 8) {
        int qr = r0 + rr;
        if (qr < N_) {
            float mx = -1e30f;
            for (int i = lane; i < N_; i += 32) mx = fmaxf(mx, S[rr * NPADS + i]);
#pragma unroll
            for (int o = 16; o; o >>= 1) mx = fmaxf(mx, __shfl_xor_sync(0xffffffffu, mx, o));
            float s = 0.0f;
            for (int i = lane; i < NPADS; i += 32) {
                if (i < N_) {
                    float e = __expf(S[rr * NPADS + i] - mx);
                    S[rr * NPADS + i] = e;
                    s += e;
                } else S[rr * NPADS + i] = 0.0f;
            }
#pragma unroll
            for (int o = 16; o; o >>= 1) s += __shfl_xor_sync(0xffffffffu, s, o);
            float inv = 1.0f / s;
            float* arow = outf + attn_base +
                ((((size_t)b * T_ + t) * L_ + l) * N_ + qr) * (size_t)N_;
            for (int i = lane; i < N_; i += 32) {
                float p = S[rr * NPADS + i] * inv;
                S[rr * NPADS + i] = p;
                arow[i] = p;
            }
        } else {
            for (int i = lane; i < NPADS; i += 32) S[rr * NPADS + i] = 0.0f;
        }
    }

    // ----- Phase 2: O = P V + bias -----
    float acc2[5][6] = {};
    for (int kc = 0; kc < 11; kc++) {
        const int kb = kc * 32;
        __syncthreads();
        for (int idx = tid; idx < 32 * 48; idx += 256) {
            int key = idx / 48, c4 = idx % 48;
            int gk = kb + key;
            float4 v = make_float4(0.f, 0.f, 0.f, 0.f);
            if (gk < N_) v = *(const float4*)(Vg + (size_t)gk * G_ + 4 * c4);
            *(float4*)&CH[key * VSTR + 4 * c4] = v;
        }
        __syncthreads();
#pragma unroll
        for (int kk = 0; kk < 32; kk += 4) {
            float4 p[5];
#pragma unroll
            for (int m = 0; m < 5; m++)
                p[m] = *(const float4*)&S[(w + 8 * m) * NPADS + kb + kk];
#pragma unroll
            for (int j = 0; j < 6; j++) {
                const int cv = lane + 32 * j;
                float v0 = CH[kk * VSTR + cv];
                float v1 = CH[(kk + 1) * VSTR + cv];
                float v2 = CH[(kk + 2) * VSTR + cv];
                float v3 = CH[(kk + 3) * VSTR + cv];
#pragma unroll
                for (int m = 0; m < 5; m++)
                    acc2[m][j] += p[m].x * v0 + p[m].y * v1 + p[m].z * v2 + p[m].w * v3;
            }
        }
    }

    const float* bias = (g == 0 ? b_i : b_h) + (size_t)l * G_;
    float* Og = g_O[g] + (size_t)b * N_ * G_;
#pragma unroll
    for (int m = 0; m < 5; m++) {
        int qr = r0 + w + 8 * m;
        if (qr < N_) {
#pragma unroll
            for (int j = 0; j < 6; j++) {
                int c = lane + 32 * j;
                Og[(size_t)qr * G_ + c] = acc2[m][j] + bias[c];
            }
        }
    }
}

// ---------------------------------------------------------------------------
// GRU gating + LayerNorm. block 256 (4 rows x 64), grid 1300
// ---------------------------------------------------------------------------
__global__ void gate_kernel(int t, int l,
                            const float* __restrict__ ln_g, const float* __restrict__ ln_b,
                            float* __restrict__ outf) {
    __shared__ float s_s[8], s_q[8];
    const int tid  = threadIdx.x;
    const int rloc = tid >> 6;
    const int d    = tid & 63;
    const int row  = blockIdx.x * 4 + rloc;
    const int valid = (row < BN);

    float o = 0.0f;
    int b = 0, n = 0;
    if (valid) {
        b = row / N_; n = row - b * N_;
        const float* oi = g_O[0] + (size_t)row * G_;
        const float* oh = g_O[1] + (size_t)row * G_;
        const float* hid = outf + OFF_HID + (((size_t)b * L_ + l) * N_ + n) * D_;
        float h  = hid[d];
        float rg = 1.0f / (1.0f + expf(-(oi[d]       + oh[d])));
        float ig = 1.0f / (1.0f + expf(-(oi[64 + d]  + oh[64 + d])));
        float ng = tanhf(oi[128 + d] + rg * oh[128 + d]);
        o = ng + ig * (h - ng);
    }

    float s = o, q = o * o;
#pragma unroll
    for (int off = 16; off; off >>= 1) {
        s += __shfl_xor_sync(0xffffffffu, s, off);
        q += __shfl_xor_sync(0xffffffffu, q, off);
    }
    const int w = tid >> 5;
    if ((tid & 31) == 0) { s_s[w] = s; s_q[w] = q; }
    __syncthreads();

    if (valid) {
        int w0 = rloc * 2;
        float sum = s_s[w0] + s_s[w0 + 1];
        float sq  = s_q[w0] + s_q[w0 + 1];
        float mu  = sum * (1.0f / 64.0f);
        float var = sq * (1.0f / 64.0f) - mu * mu;
        float y = (o - mu) * rsqrtf(var + 1e-5f) * ln_g[l * D_ + d] + ln_b[l * D_ + d];
        float* hid = outf + OFF_HID + (((size_t)b * L_ + l) * N_ + n) * D_;
        hid[d] = y;
        g_X[(size_t)row * D_ + d] = y;
        if (l == L_ - 1)
            outf[(((size_t)b * T_ + t) * N_ + n) * D_ + d] = y;
    }
}

// ---------------------------------------------------------------------------
extern "C" void kernel_launch(void* const* d_in, const int* in_sizes, int n_in,
                              void* d_out, int out_size) {
    const float* x    = (const float*)d_in[0];
    const float* Wq_i = (const float*)d_in[1];
    const float* Wk_i = (const float*)d_in[2];
    const float* Wv_i = (const float*)d_in[3];
    const float* b_i  = (const float*)d_in[4];
    const float* Wq_h = (const float*)d_in[5];
    const float* Wk_h = (const float*)d_in[6];
    const float* Wv_h = (const float*)d_in[7];
    const float* b_h  = (const float*)d_in[8];
    const float* ln_g = (const float*)d_in[9];
    const float* ln_b = (const float*)d_in[10];
    float* outf = (float*)d_out;

    const int attn_smem = ATTN_SMEM_FLOATS * (int)sizeof(float); // 100,480 B
    cudaFuncSetAttribute(attn_kernel, cudaFuncAttributeMaxDynamicSharedMemorySize, attn_smem);

    zero_hidden_kernel<<<(int)((SZ_HID + 255) / 256), 256>>>(outf);

    dim3 qkv_grid(82, 10);
    dim3 attn_grid(NTILES, 2, 16);
    const int gate_grid = (BN + 3) / 4;

    for (int t = 0; t < T_; t++) {
        for (int l = 0; l < L_; l++) {
            int from_x = (l == 0) ? 1 : 0;
            qkv_kernel<<<qkv_grid, 256>>>(t, l, from_x, x,
                                          Wq_i, Wk_i, Wv_i, Wq_h, Wk_h, Wv_h);
            attn_kernel<<<attn_grid, 256, attn_smem>>>(t, l, b_i, b_h, outf);
            gate_kernel<<<gate_grid, 256>>>(t, l, ln_g, ln_b, outf);
        }
    }
}

// round 3
// speedup vs baseline: 1.9104x; 1.2400x over previous
#include <cuda_runtime.h>
#include <cuda_bf16.h>
#include <math.h>

// Problem constants
#define B_  16
#define T_  12
#define N_  325
#define D_  64
#define L_  2
#define G_  192
#define BN  (B_ * N_)          // 5200

// d_out layout (floats): output, hidden, attn_input, attn_hidden
#define SZ_OUT ((size_t)B_ * T_ * N_ * D_)
#define SZ_HID ((size_t)B_ * L_ * N_ * D_)
#define SZ_A   ((size_t)B_ * T_ * L_ * N_ * N_)
#define OFF_OUT 0
#define OFF_HID (SZ_OUT)
#define OFF_AI  (SZ_OUT + SZ_HID)
#define OFF_AH  (SZ_OUT + SZ_HID + SZ_A)

// Scratch (device globals -- no allocation allowed)
__device__ float g_X[BN * D_];            // current layer input
__device__ float g_Q[2][BN * D_];
__device__ float g_K[2][BN * D_];
__device__ float g_PX[2][BN * D_];        // attn @ x   (per gat)
__device__ float g_O[2][BN * G_];         // (attn@x) @ Wv + bias

// ---------------------------------------------------------------------------
__global__ void zero_hidden_kernel(float* __restrict__ outf) {
    size_t i = (size_t)blockIdx.x * blockDim.x + threadIdx.x;
    if (i < SZ_HID) outf[OFF_HID + i] = 0.0f;
}

// ---------------------------------------------------------------------------
// Q/K GEMM: X:(BN,64) @ {Wq,Wk} x {input-gat, hidden-gat}
// grid = (82, 4), block = 256.  cb: 0:Qi 1:Ki 2:Qh 3:Kh
// ---------------------------------------------------------------------------
__global__ void qk_kernel(int t, int l, int from_x,
                          const float* __restrict__ x,
                          const float* __restrict__ Wq_i, const float* __restrict__ Wk_i,
                          const float* __restrict__ Wq_h, const float* __restrict__ Wk_h) {
    __shared__ float Xs[64][65];
    __shared__ float Ws[64][65];

    const int rb  = blockIdx.x;
    const int cb  = blockIdx.y;
    const int tid = threadIdx.x;

    const float* src;
    long bstr;
    if (from_x) { src = x + (size_t)t * N_ * D_; bstr = (long)T_ * N_ * D_; }
    else        { src = g_X;                     bstr = (long)N_ * D_; }

    for (int idx = tid; idx < 64 * 64; idx += 256) {
        int r = idx >> 6, k = idx & 63;
        int row = rb * 64 + r;
        float v = 0.0f;
        if (row < BN) {
            int bb = row / N_, n = row - bb * N_;
            v = src[(size_t)bb * bstr + n * D_ + k];
        }
        Xs[r][k] = v;
    }

    const int g    = cb >> 1;         // 0: input-gat, 1: hidden-gat
    const int isK  = cb & 1;
    const float* W = (g ? (isK ? Wk_h : Wq_h) : (isK ? Wk_i : Wq_i)) + (size_t)l * D_ * D_;

    for (int idx = tid; idx < 64 * 64; idx += 256) {
        int k = idx >> 6, c = idx & 63;
        Ws[k][c] = W[k * 64 + c];
    }
    __syncthreads();

    const int ty = tid >> 4, tx = tid & 15;
    float acc[4][4] = {};
#pragma unroll 8
    for (int k = 0; k < 64; k++) {
        float xv[4], wv[4];
#pragma unroll
        for (int m = 0; m < 4; m++) xv[m] = Xs[ty + 16 * m][k];
#pragma unroll
        for (int j = 0; j < 4; j++) wv[j] = Ws[k][tx + 16 * j];
#pragma unroll
        for (int m = 0; m < 4; m++)
#pragma unroll
            for (int j = 0; j < 4; j++) acc[m][j] += xv[m] * wv[j];
    }

    float* dst = isK ? g_K[g] : g_Q[g];
#pragma unroll
    for (int m = 0; m < 4; m++) {
        int row = rb * 64 + ty + 16 * m;
        if (row < BN) {
#pragma unroll
            for (int j = 0; j < 4; j++)
                dst[(size_t)row * 64 + tx + 16 * j] = acc[m][j];
        }
    }
}

// ---------------------------------------------------------------------------
// Fused attention: S = QK^T/8 -> softmax -> write attn -> PX = P @ x
// grid (9, 2, 16), block 256, RT=40 rows/block.
// ---------------------------------------------------------------------------
#define RT     40
#define NTILES 9
#define NPADS  352
#define QSTR   68
#define KSTR   65

#define ATTN_SMEM_FLOATS (RT * QSTR + RT * NPADS + 128 * KSTR)

__global__ void attn_kernel(int t, int l, int from_x,
                            const float* __restrict__ x,
                            float* __restrict__ outf) {
    extern __shared__ float sm[];
    float* Qs = sm;                         // RT x QSTR
    float* S  = sm + RT * QSTR;             // RT x NPADS
    float* CH = S + RT * NPADS;             // K: 128 x KSTR  /  x: 64 x KSTR

    const int rt   = blockIdx.x;
    const int g    = blockIdx.y;
    const int b    = blockIdx.z;
    const int tid  = threadIdx.x;
    const int w    = tid >> 5;
    const int lane = tid & 31;
    const int r0   = rt * RT;

    const float* Qg = g_Q[g] + (size_t)b * N_ * D_;
    const float* Kg = g_K[g] + (size_t)b * N_ * D_;

    const float* xsrc;
    if (from_x) xsrc = x + (((size_t)b * T_ + t) * N_) * D_;
    else        xsrc = g_X + (size_t)b * N_ * D_;

    // load Q tile
    for (int idx = tid; idx < RT * 64; idx += 256) {
        int r = idx >> 6, d = idx & 63;
        int qr = r0 + r;
        Qs[r * QSTR + d] = (qr < N_) ? Qg[(size_t)qr * D_ + d] : 0.0f;
    }

    // ----- Phase 1: S = Q K^T / 8 -----
    for (int kc = 0; kc < 3; kc++) {
        const int kb = kc * 128;
        __syncthreads();
        for (int idx = tid; idx < 128 * 16; idx += 256) {
            int key = idx >> 4, d4 = idx & 15;
            int gk = kb + key;
            float4 v = make_float4(0.f, 0.f, 0.f, 0.f);
            if (gk < N_) v = *(const float4*)(Kg + (size_t)gk * D_ + 4 * d4);
            int base = key * KSTR + 4 * d4;
            CH[base] = v.x; CH[base + 1] = v.y; CH[base + 2] = v.z; CH[base + 3] = v.w;
        }
        __syncthreads();

        float acc[5][4] = {};
#pragma unroll
        for (int k = 0; k < 64; k += 4) {
            float4 q[5];
#pragma unroll
            for (int m = 0; m < 5; m++)
                q[m] = *(const float4*)&Qs[(w + 8 * m) * QSTR + k];
#pragma unroll
            for (int j = 0; j < 4; j++) {
                const int ck = (lane + 32 * j) * KSTR + k;
                float k0 = CH[ck], k1 = CH[ck + 1], k2 = CH[ck + 2], k3 = CH[ck + 3];
#pragma unroll
                for (int m = 0; m < 5; m++)
                    acc[m][j] += q[m].x * k0 + q[m].y * k1 + q[m].z * k2 + q[m].w * k3;
            }
        }
#pragma unroll
        for (int j = 0; j < 4; j++) {
            int c = kb + lane + 32 * j;
            if (c < NPADS) {
#pragma unroll
                for (int m = 0; m < 5; m++)
                    S[(w + 8 * m) * NPADS + c] = acc[m][j] * 0.125f;
            }
        }
    }
    __syncthreads();

    // ----- Softmax + write attn to d_out -----
    const size_t attn_base = (g == 0 ? OFF_AI : OFF_AH);
    for (int rr = w; rr < RT; rr += 8) {
        int qr = r0 + rr;
        if (qr < N_) {
            float mx = -1e30f;
            for (int i = lane; i < N_; i += 32) mx = fmaxf(mx, S[rr * NPADS + i]);
#pragma unroll
            for (int o = 16; o; o >>= 1) mx = fmaxf(mx, __shfl_xor_sync(0xffffffffu, mx, o));
            float s = 0.0f;
            for (int i = lane; i < NPADS; i += 32) {
                if (i < N_) {
                    float e = __expf(S[rr * NPADS + i] - mx);
                    S[rr * NPADS + i] = e;
                    s += e;
                } else S[rr * NPADS + i] = 0.0f;
            }
#pragma unroll
            for (int o = 16; o; o >>= 1) s += __shfl_xor_sync(0xffffffffu, s, o);
            float inv = 1.0f / s;
            float* arow = outf + attn_base +
                ((((size_t)b * T_ + t) * L_ + l) * N_ + qr) * (size_t)N_;
            for (int i = lane; i < N_; i += 32) {
                float p = S[rr * NPADS + i] * inv;
                S[rr * NPADS + i] = p;
                arow[i] = p;
            }
        } else {
            for (int i = lane; i < NPADS; i += 32) S[rr * NPADS + i] = 0.0f;
        }
    }

    // ----- Phase 2: PX = P @ x  (RT x 64), per-thread 5x2 tile -----
    float acc2[5][2] = {};
    for (int kc = 0; kc < 6; kc++) {
        const int kb = kc * 64;
        __syncthreads();
        for (int idx = tid; idx < 64 * 16; idx += 256) {
            int key = idx >> 4, d4 = idx & 15;
            int gk = kb + key;
            float4 v = make_float4(0.f, 0.f, 0.f, 0.f);
            if (gk < N_) v = *(const float4*)(xsrc + (size_t)gk * D_ + 4 * d4);
            int base = key * KSTR + 4 * d4;
            CH[base] = v.x; CH[base + 1] = v.y; CH[base + 2] = v.z; CH[base + 3] = v.w;
        }
        __syncthreads();
#pragma unroll
        for (int kk = 0; kk < 64; kk += 4) {
            float4 p[5];
#pragma unroll
            for (int m = 0; m < 5; m++)
                p[m] = *(const float4*)&S[(w + 8 * m) * NPADS + kb + kk];
#pragma unroll
            for (int j = 0; j < 2; j++) {
                const int c = lane + 32 * j;
                float x0 = CH[(kk)     * KSTR + c];
                float x1 = CH[(kk + 1) * KSTR + c];
                float x2 = CH[(kk + 2) * KSTR + c];
                float x3 = CH[(kk + 3) * KSTR + c];
#pragma unroll
                for (int m = 0; m < 5; m++)
                    acc2[m][j] += p[m].x * x0 + p[m].y * x1 + p[m].z * x2 + p[m].w * x3;
            }
        }
    }

    float* PXg = g_PX[g] + (size_t)b * N_ * D_;
#pragma unroll
    for (int m = 0; m < 5; m++) {
        int qr = r0 + w + 8 * m;
        if (qr < N_) {
#pragma unroll
            for (int j = 0; j < 2; j++)
                PXg[(size_t)qr * D_ + lane + 32 * j] = acc2[m][j];
        }
    }
}

// ---------------------------------------------------------------------------
// PXW GEMM: O = PX @ Wv + bias.  grid (82, 6), block 256.
// cb: g = cb>=3, c3 = cb - 3g -> column block of 64 within G=192
// ---------------------------------------------------------------------------
__global__ void pxw_kernel(int l,
                           const float* __restrict__ Wv_i, const float* __restrict__ Wv_h,
                           const float* __restrict__ b_i, const float* __restrict__ b_h) {
    __shared__ float Xs[64][65];
    __shared__ float Ws[64][65];

    const int rb  = blockIdx.x;
    const int cb  = blockIdx.y;
    const int tid = threadIdx.x;
    const int g   = (cb >= 3) ? 1 : 0;
    const int c3  = cb - 3 * g;
    const int coff = c3 * 64;

    const float* PX = g_PX[g];
    for (int idx = tid; idx < 64 * 64; idx += 256) {
        int r = idx >> 6, k = idx & 63;
        int row = rb * 64 + r;
        Xs[r][k] = (row < BN) ? PX[(size_t)row * 64 + k] : 0.0f;
    }

    const float* W = (g ? Wv_h : Wv_i) + (size_t)l * D_ * G_;
    for (int idx = tid; idx < 64 * 64; idx += 256) {
        int k = idx >> 6, c = idx & 63;
        Ws[k][c] = W[k * G_ + coff + c];
    }
    __syncthreads();

    const int ty = tid >> 4, tx = tid & 15;
    float acc[4][4] = {};
#pragma unroll 8
    for (int k = 0; k < 64; k++) {
        float xv[4], wv[4];
#pragma unroll
        for (int m = 0; m < 4; m++) xv[m] = Xs[ty + 16 * m][k];
#pragma unroll
        for (int j = 0; j < 4; j++) wv[j] = Ws[k][tx + 16 * j];
#pragma unroll
        for (int m = 0; m < 4; m++)
#pragma unroll
            for (int j = 0; j < 4; j++) acc[m][j] += xv[m] * wv[j];
    }

    const float* bias = (g ? b_h : b_i) + (size_t)l * G_;
    float* dst = g_O[g];
#pragma unroll
    for (int m = 0; m < 4; m++) {
        int row = rb * 64 + ty + 16 * m;
        if (row < BN) {
#pragma unroll
            for (int j = 0; j < 4; j++) {
                int c = coff + tx + 16 * j;
                dst[(size_t)row * G_ + c] = acc[m][j] + bias[c];
            }
        }
    }
}

// ---------------------------------------------------------------------------
// GRU gating + LayerNorm. block 256 (4 rows x 64), grid 1300
// ---------------------------------------------------------------------------
__global__ void gate_kernel(int t, int l,
                            const float* __restrict__ ln_g, const float* __restrict__ ln_b,
                            float* __restrict__ outf) {
    __shared__ float s_s[8], s_q[8];
    const int tid  = threadIdx.x;
    const int rloc = tid >> 6;
    const int d    = tid & 63;
    const int row  = blockIdx.x * 4 + rloc;
    const int valid = (row < BN);

    float o = 0.0f;
    int b = 0, n = 0;
    if (valid) {
        b = row / N_; n = row - b * N_;
        const float* oi = g_O[0] + (size_t)row * G_;
        const float* oh = g_O[1] + (size_t)row * G_;
        const float* hid = outf + OFF_HID + (((size_t)b * L_ + l) * N_ + n) * D_;
        float h  = hid[d];
        float rg = 1.0f / (1.0f + expf(-(oi[d]       + oh[d])));
        float ig = 1.0f / (1.0f + expf(-(oi[64 + d]  + oh[64 + d])));
        float ng = tanhf(oi[128 + d] + rg * oh[128 + d]);
        o = ng + ig * (h - ng);
    }

    float s = o, q = o * o;
#pragma unroll
    for (int off = 16; off; off >>= 1) {
        s += __shfl_xor_sync(0xffffffffu, s, off);
        q += __shfl_xor_sync(0xffffffffu, q, off);
    }
    const int w = tid >> 5;
    if ((tid & 31) == 0) { s_s[w] = s; s_q[w] = q; }
    __syncthreads();

    if (valid) {
        int w0 = rloc * 2;
        float sum = s_s[w0] + s_s[w0 + 1];
        float sq  = s_q[w0] + s_q[w0 + 1];
        float mu  = sum * (1.0f / 64.0f);
        float var = sq * (1.0f / 64.0f) - mu * mu;
        float y = (o - mu) * rsqrtf(var + 1e-5f) * ln_g[l * D_ + d] + ln_b[l * D_ + d];
        float* hid = outf + OFF_HID + (((size_t)b * L_ + l) * N_ + n) * D_;
        hid[d] = y;
        g_X[(size_t)row * D_ + d] = y;
        if (l == L_ - 1)
            outf[(((size_t)b * T_ + t) * N_ + n) * D_ + d] = y;
    }
}

// ---------------------------------------------------------------------------
extern "C" void kernel_launch(void* const* d_in, const int* in_sizes, int n_in,
                              void* d_out, int out_size) {
    const float* x    = (const float*)d_in[0];
    const float* Wq_i = (const float*)d_in[1];
    const float* Wk_i = (const float*)d_in[2];
    const float* Wv_i = (const float*)d_in[3];
    const float* b_i  = (const float*)d_in[4];
    const float* Wq_h = (const float*)d_in[5];
    const float* Wk_h = (const float*)d_in[6];
    const float* Wv_h = (const float*)d_in[7];
    const float* b_h  = (const float*)d_in[8];
    const float* ln_g = (const float*)d_in[9];
    const float* ln_b = (const float*)d_in[10];
    float* outf = (float*)d_out;

    const int attn_smem = ATTN_SMEM_FLOATS * (int)sizeof(float); // 100,480 B
    cudaFuncSetAttribute(attn_kernel, cudaFuncAttributeMaxDynamicSharedMemorySize, attn_smem);

    zero_hidden_kernel<<<(int)((SZ_HID + 255) / 256), 256>>>(outf);

    dim3 qk_grid(82, 4);
    dim3 attn_grid(NTILES, 2, 16);
    dim3 pxw_grid(82, 6);
    const int gate_grid = (BN + 3) / 4;

    for (int t = 0; t < T_; t++) {
        for (int l = 0; l < L_; l++) {
            int from_x = (l == 0) ? 1 : 0;
            qk_kernel<<<qk_grid, 256>>>(t, l, from_x, x, Wq_i, Wk_i, Wq_h, Wk_h);
            attn_kernel<<<attn_grid, 256, attn_smem>>>(t, l, from_x, x, outf);
            pxw_kernel<<<pxw_grid, 256>>>(l, Wv_i, Wv_h, b_i, b_h);
            gate_kernel<<<gate_grid, 256>>>(t, l, ln_g, ln_b, outf);
        }
    }
}

// round 4
// speedup vs baseline: 2.2748x; 1.1907x over previous
#include <cuda_runtime.h>
#include <cuda_bf16.h>
#include <math.h>

// Problem constants
#define B_  16
#define T_  12
#define N_  325
#define D_  64
#define L_  2
#define G_  192
#define BN  (B_ * N_)          // 5200

// d_out layout (floats): output, hidden, attn_input, attn_hidden
#define SZ_OUT ((size_t)B_ * T_ * N_ * D_)
#define SZ_HID ((size_t)B_ * L_ * N_ * D_)
#define SZ_A   ((size_t)B_ * T_ * L_ * N_ * N_)
#define OFF_OUT 0
#define OFF_HID (SZ_OUT)
#define OFF_AI  (SZ_OUT + SZ_HID)
#define OFF_AH  (SZ_OUT + SZ_HID + SZ_A)

// Scratch (device globals -- no allocation allowed)
__device__ float g_X[BN * D_];            // current layer input
__device__ float g_Q[2][BN * D_];
__device__ float g_K[2][BN * D_];
__device__ float g_O[2][BN * G_];         // gat outputs ((attn@x)@Wv + bias)

typedef unsigned long long ull;

// packed f32x2 helpers (sm_100+)
__device__ __forceinline__ void ffma2(ull& d, ull a, ull b) {
    asm volatile("fma.rn.f32x2 %0, %1, %2, %0;" : "+l"(d) : "l"(a), "l"(b));
}
__device__ __forceinline__ float f2sum(ull v) {
    float lo, hi;
    asm("mov.b64 {%0, %1}, %2;" : "=f"(lo), "=f"(hi) : "l"(v));
    return lo + hi;
}
__device__ __forceinline__ ull dup2(float v) {
    ull r;
    asm("mov.b64 %0, {%1, %1};" : "=l"(r) : "f"(v));
    return r;
}
__device__ __forceinline__ void unpk(ull v, float& lo, float& hi) {
    asm("mov.b64 {%0, %1}, %2;" : "=f"(lo), "=f"(hi) : "l"(v));
}

// ---------------------------------------------------------------------------
__global__ void zero_hidden_kernel(float* __restrict__ outf) {
    size_t i = (size_t)blockIdx.x * blockDim.x + threadIdx.x;
    if (i < SZ_HID) outf[OFF_HID + i] = 0.0f;
}

// ---------------------------------------------------------------------------
// Q/K GEMM (f32x2): grid (82, 4), block 256.  cb: 0:Qi 1:Ki 2:Qh 3:Kh
// ---------------------------------------------------------------------------
__global__ void qk_kernel(int t, int l, int from_x,
                          const float* __restrict__ x,
                          const float* __restrict__ Wq_i, const float* __restrict__ Wk_i,
                          const float* __restrict__ Wq_h, const float* __restrict__ Wk_h) {
    __shared__ float Xs[64 * 68];       // [row][k]
    __shared__ float Wt[64 * 66];       // [c][k] (transposed weights)

    const int rb  = blockIdx.x;
    const int cb  = blockIdx.y;
    const int tid = threadIdx.x;

    const float* src;
    long bstr;
    if (from_x) { src = x + (size_t)t * N_ * D_; bstr = (long)T_ * N_ * D_; }
    else        { src = g_X;                     bstr = (long)N_ * D_; }

    for (int idx = tid; idx < 64 * 64; idx += 256) {
        int r = idx >> 6, k = idx & 63;
        int row = rb * 64 + r;
        float v = 0.0f;
        if (row < BN) {
            int bb = row / N_, n = row - bb * N_;
            v = src[(size_t)bb * bstr + n * D_ + k];
        }
        Xs[r * 68 + k] = v;
    }

    const int g   = cb >> 1;
    const int isK = cb & 1;
    const float* W = (g ? (isK ? Wk_h : Wq_h) : (isK ? Wk_i : Wq_i)) + (size_t)l * D_ * D_;

    for (int idx = tid; idx < 64 * 64; idx += 256) {
        int k = idx >> 6, c = idx & 63;
        Wt[c * 66 + k] = W[k * 64 + c];
    }
    __syncthreads();

    const int ty = tid >> 4, tx = tid & 15;
    ull acc[4][4] = {};
#pragma unroll
    for (int k = 0; k < 64; k += 4) {
        ulonglong2 xv[4];
#pragma unroll
        for (int m = 0; m < 4; m++)
            xv[m] = *(const ulonglong2*)&Xs[(ty + 16 * m) * 68 + k];
#pragma unroll
        for (int j = 0; j < 4; j++) {
            const int c = tx + 16 * j;
            ull w0 = *(const ull*)&Wt[c * 66 + k];
            ull w1 = *(const ull*)&Wt[c * 66 + k + 2];
#pragma unroll
            for (int m = 0; m < 4; m++) {
                ffma2(acc[m][j], xv[m].x, w0);
                ffma2(acc[m][j], xv[m].y, w1);
            }
        }
    }

    float* dst = isK ? g_K[g] : g_Q[g];
#pragma unroll
    for (int m = 0; m < 4; m++) {
        int row = rb * 64 + ty + 16 * m;
        if (row < BN) {
#pragma unroll
            for (int j = 0; j < 4; j++)
                dst[(size_t)row * 64 + tx + 16 * j] = f2sum(acc[m][j]);
        }
    }
}

// ---------------------------------------------------------------------------
// Fused attention + PXW epilogue (all f32x2):
//   S = QK^T/8 -> softmax -> write attn -> PX = P@x -> O = PX@Wv + bias
// grid (9, 2, 16), block 256, RT=40 rows/block.
// ---------------------------------------------------------------------------
#define RT     40
#define NTILES 9
#define NPADS  384
#define QSTR   68
#define KSTR   66

#define SM_QS  0
#define SM_S   (RT * QSTR)                  // 2720
#define SM_CH  (SM_S + RT * NPADS)          // 2720 + 15360 = 18080
#define ATTN_SMEM_FLOATS (SM_CH + 128 * KSTR)   // + 8448 = 26528

__global__ void attn_kernel(int t, int l, int from_x,
                            const float* __restrict__ x,
                            const float* __restrict__ Wv_i, const float* __restrict__ Wv_h,
                            const float* __restrict__ b_i,  const float* __restrict__ b_h,
                            float* __restrict__ outf) {
    extern __shared__ float sm[];
    float* Qs = sm + SM_QS;                 // RT x QSTR   (Q, later PX)
    float* S  = sm + SM_S;                  // RT x NPADS  (scores/P, later Wt)
    float* CH = sm + SM_CH;                 // K: [c][k] 128x66 / x: [key][c] 64x66

    const int rt   = blockIdx.x;
    const int g    = blockIdx.y;
    const int b    = blockIdx.z;
    const int tid  = threadIdx.x;
    const int w    = tid >> 5;
    const int lane = tid & 31;
    const int r0   = rt * RT;

    const float* Qg = g_Q[g] + (size_t)b * N_ * D_;
    const float* Kg = g_K[g] + (size_t)b * N_ * D_;

    const float* xsrc;
    if (from_x) xsrc = x + (((size_t)b * T_ + t) * N_) * D_;
    else        xsrc = g_X + (size_t)b * N_ * D_;

    // load Q tile
    for (int idx = tid; idx < RT * 64; idx += 256) {
        int r = idx >> 6, d = idx & 63;
        int qr = r0 + r;
        Qs[r * QSTR + d] = (qr < N_) ? Qg[(size_t)qr * D_ + d] : 0.0f;
    }

    // ----- Phase 1: S = Q K^T / 8  (pack over k) -----
    for (int kc = 0; kc < 3; kc++) {
        const int kb = kc * 128;
        __syncthreads();
        for (int idx = tid; idx < 128 * 16; idx += 256) {
            int key = idx >> 4, d4 = idx & 15;
            int gk = kb + key;
            float4 v = make_float4(0.f, 0.f, 0.f, 0.f);
            if (gk < N_) v = *(const float4*)(Kg + (size_t)gk * D_ + 4 * d4);
            int base = key * KSTR + 4 * d4;
            *(float2*)&CH[base]     = make_float2(v.x, v.y);
            *(float2*)&CH[base + 2] = make_float2(v.z, v.w);
        }
        __syncthreads();

        ull acc[5][4] = {};
#pragma unroll
        for (int k = 0; k < 64; k += 4) {
            ulonglong2 q[5];
#pragma unroll
            for (int m = 0; m < 5; m++)
                q[m] = *(const ulonglong2*)&Qs[(w + 8 * m) * QSTR + k];
#pragma unroll
            for (int j = 0; j < 4; j++) {
                const int c = lane + 32 * j;
                ull k0 = *(const ull*)&CH[c * KSTR + k];
                ull k1 = *(const ull*)&CH[c * KSTR + k + 2];
#pragma unroll
                for (int m = 0; m < 5; m++) {
                    ffma2(acc[m][j], q[m].x, k0);
                    ffma2(acc[m][j], q[m].y, k1);
                }
            }
        }
#pragma unroll
        for (int j = 0; j < 4; j++) {
            int c = kb + lane + 32 * j;
#pragma unroll
            for (int m = 0; m < 5; m++)
                S[(w + 8 * m) * NPADS + c] = f2sum(acc[m][j]) * 0.125f;
        }
    }
    __syncthreads();

    // ----- Softmax + write attn to d_out -----
    const size_t attn_base = (g == 0 ? OFF_AI : OFF_AH);
    for (int rr = w; rr < RT; rr += 8) {
        int qr = r0 + rr;
        if (qr < N_) {
            float mx = -1e30f;
            for (int i = lane; i < N_; i += 32) mx = fmaxf(mx, S[rr * NPADS + i]);
#pragma unroll
            for (int o = 16; o; o >>= 1) mx = fmaxf(mx, __shfl_xor_sync(0xffffffffu, mx, o));
            float s = 0.0f;
            for (int i = lane; i < NPADS; i += 32) {
                if (i < N_) {
                    float e = __expf(S[rr * NPADS + i] - mx);
                    S[rr * NPADS + i] = e;
                    s += e;
                } else S[rr * NPADS + i] = 0.0f;
            }
#pragma unroll
            for (int o = 16; o; o >>= 1) s += __shfl_xor_sync(0xffffffffu, s, o);
            float inv = 1.0f / s;
            float* arow = outf + attn_base +
                ((((size_t)b * T_ + t) * L_ + l) * N_ + qr) * (size_t)N_;
            for (int i = lane; i < N_; i += 32) {
                float p = S[rr * NPADS + i] * inv;
                S[rr * NPADS + i] = p;
                arow[i] = p;
            }
        } else {
            for (int i = lane; i < NPADS; i += 32) S[rr * NPADS + i] = 0.0f;
        }
    }

    // ----- Phase 2: PX = P @ x  (pack over column pairs) -----
    ull acc2[5] = {};
    for (int kc = 0; kc < 6; kc++) {
        const int kb = kc * 64;
        __syncthreads();
        // x chunk: [key][c], stride 66, zero-padded
        for (int idx = tid; idx < 64 * 16; idx += 256) {
            int key = idx >> 4, d4 = idx & 15;
            int gk = kb + key;
            float4 v = make_float4(0.f, 0.f, 0.f, 0.f);
            if (gk < N_) v = *(const float4*)(xsrc + (size_t)gk * D_ + 4 * d4);
            int base = key * KSTR + 4 * d4;
            *(float2*)&CH[base]     = make_float2(v.x, v.y);
            *(float2*)&CH[base + 2] = make_float2(v.z, v.w);
        }
        __syncthreads();
#pragma unroll
        for (int kk = 0; kk < 64; kk += 4) {
            float4 p[5];
#pragma unroll
            for (int m = 0; m < 5; m++)
                p[m] = *(const float4*)&S[(w + 8 * m) * NPADS + kb + kk];
            ull xv0 = *(const ull*)&CH[(kk)     * KSTR + 2 * lane];
            ull xv1 = *(const ull*)&CH[(kk + 1) * KSTR + 2 * lane];
            ull xv2 = *(const ull*)&CH[(kk + 2) * KSTR + 2 * lane];
            ull xv3 = *(const ull*)&CH[(kk + 3) * KSTR + 2 * lane];
#pragma unroll
            for (int m = 0; m < 5; m++) {
                ffma2(acc2[m], dup2(p[m].x), xv0);
                ffma2(acc2[m], dup2(p[m].y), xv1);
                ffma2(acc2[m], dup2(p[m].z), xv2);
                ffma2(acc2[m], dup2(p[m].w), xv3);
            }
        }
    }
    // store PX (halves are distinct columns 2*lane, 2*lane+1) into Qs
#pragma unroll
    for (int m = 0; m < 5; m++) {
        float lo, hi;
        unpk(acc2[m], lo, hi);
        *(float2*)&Qs[(w + 8 * m) * QSTR + 2 * lane] = make_float2(lo, hi);
    }
    __syncthreads();

    // ----- Phase 3: O = PX @ Wv + bias  (Wt transposed into S region) -----
    const float* W   = (g ? Wv_h : Wv_i) + (size_t)l * D_ * G_;
    const float* bias = (g ? b_h : b_i) + (size_t)l * G_;
    float* Wt = S;                           // [c][d], stride 66 (192*66 <= RT*NPADS)
    for (int idx = tid; idx < 64 * G_; idx += 256) {
        int d = idx / G_, c = idx % G_;
        Wt[c * 66 + d] = W[d * G_ + c];
    }
    __syncthreads();

    float* Og = g_O[g] + (size_t)b * N_ * G_;
#pragma unroll
    for (int jg = 0; jg < 2; jg++) {
        ull acc3[5][3] = {};
#pragma unroll
        for (int d = 0; d < 64; d += 4) {
            ulonglong2 px[5];
#pragma unroll
            for (int m = 0; m < 5; m++)
                px[m] = *(const ulonglong2*)&Qs[(w + 8 * m) * QSTR + d];
#pragma unroll
            for (int j = 0; j < 3; j++) {
                const int c = lane + 32 * (3 * jg + j);
                ull w0 = *(const ull*)&Wt[c * 66 + d];
                ull w1 = *(const ull*)&Wt[c * 66 + d + 2];
#pragma unroll
                for (int m = 0; m < 5; m++) {
                    ffma2(acc3[m][j], px[m].x, w0);
                    ffma2(acc3[m][j], px[m].y, w1);
                }
            }
        }
#pragma unroll
        for (int m = 0; m < 5; m++) {
            int qr = r0 + w + 8 * m;
            if (qr < N_) {
#pragma unroll
                for (int j = 0; j < 3; j++) {
                    int c = lane + 32 * (3 * jg + j);
                    Og[(size_t)qr * G_ + c] = f2sum(acc3[m][j]) + __ldg(&bias[c]);
                }
            }
        }
    }
}

// ---------------------------------------------------------------------------
// GRU gating + LayerNorm. block 256 (4 rows x 64), grid 1300
// ---------------------------------------------------------------------------
__global__ void gate_kernel(int t, int l,
                            const float* __restrict__ ln_g, const float* __restrict__ ln_b,
                            float* __restrict__ outf) {
    __shared__ float s_s[8], s_q[8];
    const int tid  = threadIdx.x;
    const int rloc = tid >> 6;
    const int d    = tid & 63;
    const int row  = blockIdx.x * 4 + rloc;
    const int valid = (row < BN);

    float o = 0.0f;
    int b = 0, n = 0;
    if (valid) {
        b = row / N_; n = row - b * N_;
        const float* oi = g_O[0] + (size_t)row * G_;
        const float* oh = g_O[1] + (size_t)row * G_;
        const float* hid = outf + OFF_HID + (((size_t)b * L_ + l) * N_ + n) * D_;
        float h  = hid[d];
        float rg = 1.0f / (1.0f + expf(-(oi[d]       + oh[d])));
        float ig = 1.0f / (1.0f + expf(-(oi[64 + d]  + oh[64 + d])));
        float ng = tanhf(oi[128 + d] + rg * oh[128 + d]);
        o = ng + ig * (h - ng);
    }

    float s = o, q = o * o;
#pragma unroll
    for (int off = 16; off; off >>= 1) {
        s += __shfl_xor_sync(0xffffffffu, s, off);
        q += __shfl_xor_sync(0xffffffffu, q, off);
    }
    const int w = tid >> 5;
    if ((tid & 31) == 0) { s_s[w] = s; s_q[w] = q; }
    __syncthreads();

    if (valid) {
        int w0 = rloc * 2;
        float sum = s_s[w0] + s_s[w0 + 1];
        float sq  = s_q[w0] + s_q[w0 + 1];
        float mu  = sum * (1.0f / 64.0f);
        float var = sq * (1.0f / 64.0f) - mu * mu;
        float y = (o - mu) * rsqrtf(var + 1e-5f) * ln_g[l * D_ + d] + ln_b[l * D_ + d];
        float* hid = outf + OFF_HID + (((size_t)b * L_ + l) * N_ + n) * D_;
        hid[d] = y;
        g_X[(size_t)row * D_ + d] = y;
        if (l == L_ - 1)
            outf[(((size_t)b * T_ + t) * N_ + n) * D_ + d] = y;
    }
}

// ---------------------------------------------------------------------------
extern "C" void kernel_launch(void* const* d_in, const int* in_sizes, int n_in,
                              void* d_out, int out_size) {
    const float* x    = (const float*)d_in[0];
    const float* Wq_i = (const float*)d_in[1];
    const float* Wk_i = (const float*)d_in[2];
    const float* Wv_i = (const float*)d_in[3];
    const float* b_i  = (const float*)d_in[4];
    const float* Wq_h = (const float*)d_in[5];
    const float* Wk_h = (const float*)d_in[6];
    const float* Wv_h = (const float*)d_in[7];
    const float* b_h  = (const float*)d_in[8];
    const float* ln_g = (const float*)d_in[9];
    const float* ln_b = (const float*)d_in[10];
    float* outf = (float*)d_out;

    const int attn_smem = ATTN_SMEM_FLOATS * (int)sizeof(float); // 106,112 B
    cudaFuncSetAttribute(attn_kernel, cudaFuncAttributeMaxDynamicSharedMemorySize, attn_smem);

    zero_hidden_kernel<<<(int)((SZ_HID + 255) / 256), 256>>>(outf);

    dim3 qk_grid(82, 4);
    dim3 attn_grid(NTILES, 2, 16);
    const int gate_grid = (BN + 3) / 4;

    for (int t = 0; t < T_; t++) {
        for (int l = 0; l < L_; l++) {
            int from_x = (l == 0) ? 1 : 0;
            qk_kernel<<<qk_grid, 256>>>(t, l, from_x, x, Wq_i, Wk_i, Wq_h, Wk_h);
            attn_kernel<<<attn_grid, 256, attn_smem>>>(t, l, from_x, x,
                                                       Wv_i, Wv_h, b_i, b_h, outf);
            gate_kernel<<<gate_grid, 256>>>(t, l, ln_g, ln_b, outf);
        }
    }
}

// round 6
// speedup vs baseline: 2.7028x; 1.1882x over previous
#include <cuda_runtime.h>
#include <cuda_bf16.h>
#include <math.h>

// Problem constants
#define B_  16
#define T_  12
#define N_  325
#define D_  64
#define L_  2
#define G_  192
#define BN  (B_ * N_)          // 5200

// d_out layout (floats): output, hidden, attn_input, attn_hidden
#define SZ_OUT ((size_t)B_ * T_ * N_ * D_)
#define SZ_HID ((size_t)B_ * L_ * N_ * D_)
#define SZ_A   ((size_t)B_ * T_ * L_ * N_ * N_)
#define OFF_OUT 0
#define OFF_HID (SZ_OUT)
#define OFF_AI  (SZ_OUT + SZ_HID)
#define OFF_AH  (SZ_OUT + SZ_HID + SZ_A)

// Scratch, parity double-buffered (stage s reads [s&1], writes [(s+1)&1])
__device__ float g_Xbuf[2][BN * D_];
__device__ float g_Qbuf[2][2][BN * D_];   // [parity][gat]
__device__ float g_Kbuf[2][2][BN * D_];

typedef unsigned long long ull;

__device__ __forceinline__ void ffma2(ull& d, ull a, ull b) {
    asm volatile("fma.rn.f32x2 %0, %1, %2, %0;" : "+l"(d) : "l"(a), "l"(b));
}
__device__ __forceinline__ float f2sum(ull v) {
    float lo, hi;
    asm("mov.b64 {%0, %1}, %2;" : "=f"(lo), "=f"(hi) : "l"(v));
    return lo + hi;
}
__device__ __forceinline__ ull dup2(float v) {
    ull r;
    asm("mov.b64 %0, {%1, %1};" : "=l"(r) : "f"(v));
    return r;
}
__device__ __forceinline__ void unpk(ull v, float& lo, float& hi) {
    asm("mov.b64 {%0, %1}, %2;" : "=f"(lo), "=f"(hi) : "l"(v));
}

// ---------------------------------------------------------------------------
__global__ void zero_hidden_kernel(float* __restrict__ outf) {
    size_t i = (size_t)blockIdx.x * blockDim.x + threadIdx.x;
    if (i < SZ_HID) outf[OFF_HID + i] = 0.0f;
}

// ---------------------------------------------------------------------------
// Prologue: Q/K for stage (t=0,l=0) from x -> parity 0.
// grid (82, 4), block 256. cb: 0:Qi 1:Ki 2:Qh 3:Kh
// ---------------------------------------------------------------------------
__global__ void qk_prologue(const float* __restrict__ x,
                            const float* __restrict__ Wq_i, const float* __restrict__ Wk_i,
                            const float* __restrict__ Wq_h, const float* __restrict__ Wk_h) {
    __shared__ float Xs[64 * 68];
    __shared__ float Wt[64 * 66];

    const int rb  = blockIdx.x;
    const int cb  = blockIdx.y;
    const int tid = threadIdx.x;

    for (int idx = tid; idx < 64 * 64; idx += 256) {
        int r = idx >> 6, k = idx & 63;
        int row = rb * 64 + r;
        float v = 0.0f;
        if (row < BN) {
            int bb = row / N_, n = row - bb * N_;
            v = x[(((size_t)bb * T_) * N_ + n) * D_ + k];   // t = 0
        }
        Xs[r * 68 + k] = v;
    }

    const int g   = cb >> 1;
    const int isK = cb & 1;
    const float* W = (g ? (isK ? Wk_h : Wq_h) : (isK ? Wk_i : Wq_i)); // l = 0

    for (int idx = tid; idx < 64 * 64; idx += 256) {
        int k = idx >> 6, c = idx & 63;
        Wt[c * 66 + k] = W[k * 64 + c];
    }
    __syncthreads();

    const int ty = tid >> 4, tx = tid & 15;
    ull acc[4][4] = {};
#pragma unroll
    for (int k = 0; k < 64; k += 4) {
        ulonglong2 xv[4];
#pragma unroll
        for (int m = 0; m < 4; m++)
            xv[m] = *(const ulonglong2*)&Xs[(ty + 16 * m) * 68 + k];
#pragma unroll
        for (int j = 0; j < 4; j++) {
            const int c = tx + 16 * j;
            ull w0 = *(const ull*)&Wt[c * 66 + k];
            ull w1 = *(const ull*)&Wt[c * 66 + k + 2];
#pragma unroll
            for (int m = 0; m < 4; m++) {
                ffma2(acc[m][j], xv[m].x, w0);
                ffma2(acc[m][j], xv[m].y, w1);
            }
        }
    }

    float* dst = isK ? g_Kbuf[0][g] : g_Qbuf[0][g];
#pragma unroll
    for (int m = 0; m < 4; m++) {
        int row = rb * 64 + ty + 16 * m;
        if (row < BN) {
#pragma unroll
            for (int j = 0; j < 4; j++)
                dst[(size_t)row * 64 + tx + 16 * j] = f2sum(acc[m][j]);
        }
    }
}

// ---------------------------------------------------------------------------
// MEGA kernel: one launch per stage. grid (9, 16), block 512.
// Warps 0-7: input-gat, warps 8-15: hidden-gat.
// ---------------------------------------------------------------------------
#define RT      40
#define NTILES  9
#define NPADS   384
#define QSTR    68
#define KSTR    66
#define QS_SZ   (RT * QSTR)          // 2720
#define S_SZ    (RT * NPADS)         // 15360
#define CH_SZ   (128 * KSTR)         // 8448
#define HALF_SZ (QS_SZ + S_SZ + CH_SZ)   // 26528
#define SMEM_FLOATS (2 * HALF_SZ)        // 53056 -> 212,224 B

__global__ __launch_bounds__(512, 1)
void mega_kernel(int t, int l, int from_x, int do_qk, int l_next, int par,
                 const float* __restrict__ x,
                 const float* __restrict__ Wq_i, const float* __restrict__ Wk_i,
                 const float* __restrict__ Wv_i, const float* __restrict__ b_i,
                 const float* __restrict__ Wq_h, const float* __restrict__ Wk_h,
                 const float* __restrict__ Wv_h, const float* __restrict__ b_h,
                 const float* __restrict__ ln_g, const float* __restrict__ ln_b,
                 float* __restrict__ outf) {
    extern __shared__ float sm[];

    const int rt    = blockIdx.x;
    const int b     = blockIdx.y;
    const int tid   = threadIdx.x;
    const int half  = tid >> 8;          // gat index
    const int tid_h = tid & 255;
    const int wl    = tid_h >> 5;        // warp within half
    const int wfull = tid >> 5;
    const int lane  = tid & 31;
    const int r0    = rt * RT;

    float* base = sm + half * HALF_SZ;
    float* Qs = base;                    // Q -> PX
    float* S  = base + QS_SZ;            // scores/P -> weight staging
    float* CH = base + QS_SZ + S_SZ;     // K / x chunks -> O staging
    float* CH0 = sm + QS_SZ + S_SZ;
    float* CH1 = sm + HALF_SZ + QS_SZ + S_SZ;
    float* Ys  = sm;                     // shared y / x_{t+1} tile (half-0 Qs)

    const float* Qg = g_Qbuf[par][half] + (size_t)b * N_ * D_;
    const float* Kg = g_Kbuf[par][half] + (size_t)b * N_ * D_;
    const float* xsrc = from_x ? x + (((size_t)b * T_ + t) * N_) * D_
                               : g_Xbuf[par] + (size_t)b * N_ * D_;

    // ---- load Q tile ----
    for (int idx = tid_h; idx < RT * 64; idx += 256) {
        int r = idx >> 6, d = idx & 63;
        int qr = r0 + r;
        Qs[r * QSTR + d] = (qr < N_) ? Qg[(size_t)qr * D_ + d] : 0.0f;
    }

    // ---- Phase 1: S = Q K^T / 8 ----
    for (int kc = 0; kc < 3; kc++) {
        const int kb = kc * 128;
        __syncthreads();
        for (int idx = tid_h; idx < 128 * 16; idx += 256) {
            int key = idx >> 4, d4 = idx & 15;
            int gk = kb + key;
            float4 v = make_float4(0.f, 0.f, 0.f, 0.f);
            if (gk < N_) v = *(const float4*)(Kg + (size_t)gk * D_ + 4 * d4);
            int bs = key * KSTR + 4 * d4;
            *(float2*)&CH[bs]     = make_float2(v.x, v.y);
            *(float2*)&CH[bs + 2] = make_float2(v.z, v.w);
        }
        __syncthreads();

        ull acc[5][4] = {};
#pragma unroll
        for (int k = 0; k < 64; k += 4) {
            ulonglong2 q[5];
#pragma unroll
            for (int m = 0; m < 5; m++)
                q[m] = *(const ulonglong2*)&Qs[(wl + 8 * m) * QSTR + k];
#pragma unroll
            for (int j = 0; j < 4; j++) {
                const int c = lane + 32 * j;
                ull k0 = *(const ull*)&CH[c * KSTR + k];
                ull k1 = *(const ull*)&CH[c * KSTR + k + 2];
#pragma unroll
                for (int m = 0; m < 5; m++) {
                    ffma2(acc[m][j], q[m].x, k0);
                    ffma2(acc[m][j], q[m].y, k1);
                }
            }
        }
#pragma unroll
        for (int j = 0; j < 4; j++) {
            int c = kb + lane + 32 * j;
#pragma unroll
            for (int m = 0; m < 5; m++)
                S[(wl + 8 * m) * NPADS + c] = f2sum(acc[m][j]) * 0.125f;
        }
    }
    __syncthreads();

    // ---- Softmax + write attn to d_out ----
    const size_t attn_base = (half == 0 ? OFF_AI : OFF_AH);
    for (int rr = wl; rr < RT; rr += 8) {
        int qr = r0 + rr;
        if (qr < N_) {
            float mx = -1e30f;
            for (int i = lane; i < N_; i += 32) mx = fmaxf(mx, S[rr * NPADS + i]);
#pragma unroll
            for (int o = 16; o; o >>= 1) mx = fmaxf(mx, __shfl_xor_sync(0xffffffffu, mx, o));
            float s = 0.0f;
            for (int i = lane; i < NPADS; i += 32) {
                if (i < N_) {
                    float e = __expf(S[rr * NPADS + i] - mx);
                    S[rr * NPADS + i] = e;
                    s += e;
                } else S[rr * NPADS + i] = 0.0f;
            }
#pragma unroll
            for (int o = 16; o; o >>= 1) s += __shfl_xor_sync(0xffffffffu, s, o);
            float inv = 1.0f / s;
            float* arow = outf + attn_base +
                ((((size_t)b * T_ + t) * L_ + l) * N_ + qr) * (size_t)N_;
            for (int i = lane; i < N_; i += 32) {
                float p = S[rr * NPADS + i] * inv;
                S[rr * NPADS + i] = p;
                arow[i] = p;
            }
        } else {
            for (int i = lane; i < NPADS; i += 32) S[rr * NPADS + i] = 0.0f;
        }
    }

    // ---- Phase 2: PX = P @ x (128-key chunks) ----
    ull acc2[5] = {};
    for (int kc = 0; kc < 3; kc++) {
        const int kb = kc * 128;
        __syncthreads();
        for (int idx = tid_h; idx < 128 * 16; idx += 256) {
            int key = idx >> 4, d4 = idx & 15;
            int gk = kb + key;
            float4 v = make_float4(0.f, 0.f, 0.f, 0.f);
            if (gk < N_) v = *(const float4*)(xsrc + (size_t)gk * D_ + 4 * d4);
            int bs = key * KSTR + 4 * d4;
            *(float2*)&CH[bs]     = make_float2(v.x, v.y);
            *(float2*)&CH[bs + 2] = make_float2(v.z, v.w);
        }
        __syncthreads();
#pragma unroll 8
        for (int kk = 0; kk < 128; kk += 4) {
            float4 p[5];
#pragma unroll
            for (int m = 0; m < 5; m++)
                p[m] = *(const float4*)&S[(wl + 8 * m) * NPADS + kb + kk];
            ull xv0 = *(const ull*)&CH[(kk)     * KSTR + 2 * lane];
            ull xv1 = *(const ull*)&CH[(kk + 1) * KSTR + 2 * lane];
            ull xv2 = *(const ull*)&CH[(kk + 2) * KSTR + 2 * lane];
            ull xv3 = *(const ull*)&CH[(kk + 3) * KSTR + 2 * lane];
#pragma unroll
            for (int m = 0; m < 5; m++) {
                ffma2(acc2[m], dup2(p[m].x), xv0);
                ffma2(acc2[m], dup2(p[m].y), xv1);
                ffma2(acc2[m], dup2(p[m].z), xv2);
                ffma2(acc2[m], dup2(p[m].w), xv3);
            }
        }
    }
#pragma unroll
    for (int m = 0; m < 5; m++) {
        float lo, hi;
        unpk(acc2[m], lo, hi);
        *(float2*)&Qs[(wl + 8 * m) * QSTR + 2 * lane] = make_float2(lo, hi);
    }
    __syncthreads();

    // ---- Phase 3: O = PX @ Wv + bias -> CH (smem) ----
    {
        const float* W    = (half ? Wv_h : Wv_i) + (size_t)l * D_ * G_;
        const float* bias = (half ? b_h : b_i) + (size_t)l * G_;
        float* Wt = S;                       // [c][d] stride 66
        for (int idx = tid_h; idx < 64 * G_; idx += 256) {
            int d = idx / G_, c = idx % G_;
            Wt[c * 66 + d] = W[d * G_ + c];
        }
        __syncthreads();

#pragma unroll
        for (int jg = 0; jg < 2; jg++) {
            ull acc3[5][3] = {};
#pragma unroll
            for (int d = 0; d < 64; d += 4) {
                ulonglong2 px[5];
#pragma unroll
                for (int m = 0; m < 5; m++)
                    px[m] = *(const ulonglong2*)&Qs[(wl + 8 * m) * QSTR + d];
#pragma unroll
                for (int j = 0; j < 3; j++) {
                    const int c = lane + 32 * (3 * jg + j);
                    ull w0 = *(const ull*)&Wt[c * 66 + d];
                    ull w1 = *(const ull*)&Wt[c * 66 + d + 2];
#pragma unroll
                    for (int m = 0; m < 5; m++) {
                        ffma2(acc3[m][j], px[m].x, w0);
                        ffma2(acc3[m][j], px[m].y, w1);
                    }
                }
            }
#pragma unroll
            for (int m = 0; m < 5; m++) {
#pragma unroll
                for (int j = 0; j < 3; j++) {
                    int c = lane + 32 * (3 * jg + j);
                    CH[(wl + 8 * m) * G_ + c] = f2sum(acc3[m][j]) + __ldg(&bias[c]);
                }
            }
        }
    }
    __syncthreads();

    // ---- Gate: GRU + LayerNorm (all 16 warps, warp-per-row) ----
    for (int rr = wfull; rr < RT; rr += 16) {
        int qr = r0 + rr;
        float o0 = 0.0f, o1 = 0.0f;
        float* hid = 0;
        if (qr < N_) {
            const float* oi = CH0 + rr * G_;
            const float* oh = CH1 + rr * G_;
            hid = outf + OFF_HID + (((size_t)b * L_ + l) * N_ + qr) * D_;
            int d0 = lane, d1 = lane + 32;
            float h0 = hid[d0], h1 = hid[d1];
            float rg0 = 1.0f / (1.0f + expf(-(oi[d0]       + oh[d0])));
            float ig0 = 1.0f / (1.0f + expf(-(oi[64 + d0]  + oh[64 + d0])));
            float ng0 = tanhf(oi[128 + d0] + rg0 * oh[128 + d0]);
            o0 = ng0 + ig0 * (h0 - ng0);
            float rg1 = 1.0f / (1.0f + expf(-(oi[d1]       + oh[d1])));
            float ig1 = 1.0f / (1.0f + expf(-(oi[64 + d1]  + oh[64 + d1])));
            float ng1 = tanhf(oi[128 + d1] + rg1 * oh[128 + d1]);
            o1 = ng1 + ig1 * (h1 - ng1);
        }
        float s = o0 + o1, q = o0 * o0 + o1 * o1;
#pragma unroll
        for (int off = 16; off; off >>= 1) {
            s += __shfl_xor_sync(0xffffffffu, s, off);
            q += __shfl_xor_sync(0xffffffffu, q, off);
        }
        if (qr < N_) {
            float mu  = s * (1.0f / 64.0f);
            float var = q * (1.0f / 64.0f) - mu * mu;
            float rs  = rsqrtf(var + 1e-5f);
            int d0 = lane, d1 = lane + 32;
            float y0 = (o0 - mu) * rs * __ldg(&ln_g[l * D_ + d0]) + __ldg(&ln_b[l * D_ + d0]);
            float y1 = (o1 - mu) * rs * __ldg(&ln_g[l * D_ + d1]) + __ldg(&ln_b[l * D_ + d1]);
            hid[d0] = y0; hid[d1] = y1;
            float* gx = g_Xbuf[par ^ 1] + ((size_t)b * N_ + qr) * D_;
            gx[d0] = y0; gx[d1] = y1;
            if (l == L_ - 1) {
                float* po = outf + OFF_OUT + (((size_t)b * T_ + t) * N_ + qr) * D_;
                po[d0] = y0; po[d1] = y1;
            }
            Ys[rr * QSTR + d0] = y0; Ys[rr * QSTR + d1] = y1;
        } else {
            Ys[rr * QSTR + lane] = 0.0f; Ys[rr * QSTR + lane + 32] = 0.0f;
        }
    }

    // ---- Epilogue: Q/K for next stage ----
    // l_next==1: input is this stage's y (already in Ys).
    // l_next==0: input is x[:, t+1] -- overwrite Ys with it.
    if (do_qk) {
        __syncthreads();
        if (l_next == 0) {
            const float* xn = x + (((size_t)b * T_ + (t + 1)) * N_) * D_;
            for (int idx = tid; idx < RT * 64; idx += 512) {
                int r = idx >> 6, d = idx & 63;
                int qr = r0 + r;
                Ys[r * QSTR + d] = (qr < N_) ? xn[(size_t)qr * D_ + d] : 0.0f;
            }
        }
        const float* Wq = (half ? Wq_h : Wq_i) + (size_t)l_next * D_ * D_;
        const float* Wk = (half ? Wk_h : Wk_i) + (size_t)l_next * D_ * D_;
        // stage transposed weights in S (per half): Wq @ 0, Wk @ 4224
        for (int idx = tid_h; idx < 64 * 64; idx += 256) {
            int d = idx >> 6, c = idx & 63;
            S[c * 66 + d]        = Wq[d * 64 + c];
            S[4224 + c * 66 + d] = Wk[d * 64 + c];
        }
        __syncthreads();

        ull aq[5][2] = {}, ak[5][2] = {};
#pragma unroll
        for (int d = 0; d < 64; d += 4) {
            ulonglong2 y4[5];
#pragma unroll
            for (int m = 0; m < 5; m++)
                y4[m] = *(const ulonglong2*)&Ys[(wl + 8 * m) * QSTR + d];
#pragma unroll
            for (int j = 0; j < 2; j++) {
                const int c = lane + 32 * j;
                ull wq0 = *(const ull*)&S[c * 66 + d];
                ull wq1 = *(const ull*)&S[c * 66 + d + 2];
                ull wk0 = *(const ull*)&S[4224 + c * 66 + d];
                ull wk1 = *(const ull*)&S[4224 + c * 66 + d + 2];
#pragma unroll
                for (int m = 0; m < 5; m++) {
                    ffma2(aq[m][j], y4[m].x, wq0);
                    ffma2(aq[m][j], y4[m].y, wq1);
                    ffma2(ak[m][j], y4[m].x, wk0);
                    ffma2(ak[m][j], y4[m].y, wk1);
                }
            }
        }
        float* Qd = g_Qbuf[par ^ 1][half] + (size_t)b * N_ * D_;
        float* Kd = g_Kbuf[par ^ 1][half] + (size_t)b * N_ * D_;
#pragma unroll
        for (int m = 0; m < 5; m++) {
            int qr = r0 + wl + 8 * m;
            if (qr < N_) {
#pragma unroll
                for (int j = 0; j < 2; j++) {
                    Qd[(size_t)qr * D_ + lane + 32 * j] = f2sum(aq[m][j]);
                    Kd[(size_t)qr * D_ + lane + 32 * j] = f2sum(ak[m][j]);
                }
            }
        }
    }
}

// ---------------------------------------------------------------------------
extern "C" void kernel_launch(void* const* d_in, const int* in_sizes, int n_in,
                              void* d_out, int out_size) {
    const float* x    = (const float*)d_in[0];
    const float* Wq_i = (const float*)d_in[1];
    const float* Wk_i = (const float*)d_in[2];
    const float* Wv_i = (const float*)d_in[3];
    const float* b_i  = (const float*)d_in[4];
    const float* Wq_h = (const float*)d_in[5];
    const float* Wk_h = (const float*)d_in[6];
    const float* Wv_h = (const float*)d_in[7];
    const float* b_h  = (const float*)d_in[8];
    const float* ln_g = (const float*)d_in[9];
    const float* ln_b = (const float*)d_in[10];
    float* outf = (float*)d_out;

    const int mega_smem = SMEM_FLOATS * (int)sizeof(float);   // 212,224 B
    cudaFuncSetAttribute(mega_kernel, cudaFuncAttributeMaxDynamicSharedMemorySize, mega_smem);

    zero_hidden_kernel<<<(int)((SZ_HID + 255) / 256), 256>>>(outf);
    qk_prologue<<<dim3(82, 4), 256>>>(x, Wq_i, Wk_i, Wq_h, Wk_h);

    dim3 mega_grid(NTILES, 16);
    for (int s = 0; s < T_ * L_; s++) {
        int t = s >> 1, l = s & 1;
        mega_kernel<<<mega_grid, 512, mega_smem>>>(
            t, l, (l == 0) ? 1 : 0, (s < T_ * L_ - 1) ? 1 : 0, l ^ 1, s & 1,
            x, Wq_i, Wk_i, Wv_i, b_i, Wq_h, Wk_h, Wv_h, b_h, ln_g, ln_b, outf);
    }
}